// round 12
// baseline (speedup 1.0000x reference)
#include <cuda_runtime.h>
#include <cuda_bf16.h>
#include <math.h>
#include <stdint.h>

#define TOKENS_MAX 4096
#define D_DIM 1024
#define V_DIM 50257
#define BM 128
#define BN 128
#define BKB 128                       // K elems (e4m3 bytes) per stage
#define N_TILES 393
#define V_PAD (N_TILES * BN)          // 50304
#define KSTEPS (D_DIM / BKB)          // 8
#define STAGES 3
#define ROW_B 144                     // padded stage row bytes
#define MAT_STAGE (BM * ROW_B)        // 18432
#define STAGE_BYTES (2 * MAT_STAGE)   // 36864
#define SM_STAGE0 128                 // stages start after mbarrier block
#define SMEM_TOTAL (SM_STAGE0 + STAGES * STAGE_BYTES) // 110720 -> 2 CTAs/SM

#define QA_SCALE 16.0f
#define QW_SCALE 64.0f
#define DEQ (1.0f / (QA_SCALE * QW_SCALE))     // 1/1024
#define DEQ_L2E (DEQ * 1.4426950408889634f)

// ---------------- device-global scratch ----------------
__device__ __align__(128) int8_t g_Wq[(size_t)V_PAD * D_DIM];
__device__ __align__(128) int8_t g_Aq[(size_t)TOKENS_MAX * D_DIM];
__device__ int   g_valid_idx[TOKENS_MAX];
__device__ int   g_tgt[TOKENS_MAX];
__device__ int   g_nvalid;
__device__ float g_sumexp[TOKENS_MAX];
__device__ float g_sumlogit[TOKENS_MAX];
__device__ float g_tlogit[TOKENS_MAX];

__device__ __forceinline__ uint32_t smem_u32(const void* p) {
    uint32_t a;
    asm("{ .reg .u64 t; cvta.to.shared.u64 t, %1; cvt.u32.u64 %0, t; }" : "=r"(a) : "l"(p));
    return a;
}
__device__ __forceinline__ void cp16(uint32_t dst, const void* src) {
    asm volatile("cp.async.cg.shared.global [%0], [%1], 16;\n" :: "r"(dst), "l"(src));
}
__device__ __forceinline__ float ex2f(float x) {
    float r;
    asm("ex2.approx.f32 %0, %1;" : "=f"(r) : "f"(x));
    return r;
}
__device__ __forceinline__ uint16_t f2e4m3x2(float hi, float lo) {
    uint16_t r;
    asm("cvt.rn.satfinite.e4m3x2.f32 %0, %1, %2;" : "=h"(r) : "f"(hi), "f"(lo));
    return r;
}
__device__ __forceinline__ uint32_t pack4_e4m3(float x0, float x1, float x2, float x3) {
    uint32_t lo = f2e4m3x2(x1, x0);
    uint32_t hi = f2e4m3x2(x3, x2);
    return lo | (hi << 16);
}
#define LDSM_X4(R0, R1, R2, R3, addr)                                          \
    asm volatile("ldmatrix.sync.aligned.m8n8.x4.shared.b16 {%0,%1,%2,%3}, [%4];" \
                 : "=r"(R0), "=r"(R1), "=r"(R2), "=r"(R3) : "r"(addr))
#define MMA_FP8(d, a, b0, b1)                                                  \
    asm volatile("mma.sync.aligned.m16n8k32.row.col.f32.e4m3.e4m3.f32 "        \
                 "{%0,%1,%2,%3}, {%4,%5,%6,%7}, {%8,%9}, {%0,%1,%2,%3};"       \
                 : "+f"((d)[0]), "+f"((d)[1]), "+f"((d)[2]), "+f"((d)[3])      \
                 : "r"((a)[0]), "r"((a)[1]), "r"((a)[2]), "r"((a)[3]),         \
                   "r"(b0), "r"(b1))
#define MBAR_INIT(addr, cnt) \
    asm volatile("mbarrier.init.shared.b64 [%0], %1;" :: "r"(addr), "r"((uint32_t)(cnt)) : "memory")
#define MBAR_ARRIVE(addr) \
    asm volatile("mbarrier.arrive.shared::cta.b64 _, [%0];" :: "r"(addr) : "memory")
#define CP_ARRIVE_NOINC(addr) \
    asm volatile("cp.async.mbarrier.arrive.noinc.shared::cta.b64 [%0];" :: "r"(addr) : "memory")
#define MBAR_WAIT(addr, par) do {                                              \
    uint32_t _m = (addr), _p = (par), _d;                                      \
    asm volatile("{\n.reg .pred p;\n"                                          \
        "mbarrier.try_wait.parity.acquire.cta.shared::cta.b64 p, [%1], %2;\n"  \
        "selp.b32 %0, 1, 0, p;\n}" : "=r"(_d) : "r"(_m), "r"(_p) : "memory");  \
    if (!_d) {                                                                 \
        asm volatile("{\n.reg .pred P1;\n"                                     \
            "W_%=:\n"                                                          \
            "mbarrier.try_wait.parity.acquire.cta.shared::cta.b64 P1, [%0], %1, 0x989680;\n" \
            "@P1 bra.uni D_%=;\n bra.uni W_%=;\nD_%=:\n}"                      \
            :: "r"(_m), "r"(_p) : "memory");                                   \
    }                                                                          \
} while (0)

// ---------------- kernel 1: mask-dtype detect + compact valid tokens ----------------
__global__ void gather_kernel(const int* __restrict__ targets,
                              const unsigned char* __restrict__ masks_raw,
                              int n_tokens) {
    __shared__ int s_isu8;
    __shared__ int wsum[32];
    int tid = threadIdx.x;
    if (tid == 0) s_isu8 = 0;
    __syncthreads();

    int flag = 0;
    for (int i = tid; i < n_tokens; i += blockDim.x)
        if ((i & 3) != 0 && masks_raw[i] != 0) flag = 1;
    if (flag) atomicOr(&s_isu8, 1);
    __syncthreads();
    const bool isu8 = (s_isu8 != 0);
    const int* masks_i32 = (const int*)masks_raw;

    int C = (n_tokens + blockDim.x - 1) / blockDim.x;
    int start = tid * C;
    int end = min(start + C, n_tokens);
    int cnt = 0;
    for (int i = start; i < end; i++)
        cnt += isu8 ? (masks_raw[i] != 0) : (masks_i32[i] != 0);

    int lane = tid & 31, wid = tid >> 5;
    int v = cnt;
    #pragma unroll
    for (int o = 1; o < 32; o <<= 1) {
        int t = __shfl_up_sync(0xffffffffu, v, o);
        if (lane >= o) v += t;
    }
    if (lane == 31) wsum[wid] = v;
    __syncthreads();
    if (wid == 0) {
        int nw = blockDim.x >> 5;
        int w = (lane < nw) ? wsum[lane] : 0;
        #pragma unroll
        for (int o = 1; o < 32; o <<= 1) {
            int t = __shfl_up_sync(0xffffffffu, w, o);
            if (lane >= o) w += t;
        }
        wsum[lane] = w;
    }
    __syncthreads();
    int excl = v - cnt + (wid > 0 ? wsum[wid - 1] : 0);

    int off = excl;
    for (int i = start; i < end; i++) {
        bool mk = isu8 ? (masks_raw[i] != 0) : (masks_i32[i] != 0);
        if (mk) {
            g_valid_idx[off] = i;
            g_tgt[off] = targets[i];
            off++;
        }
    }
    if (tid == blockDim.x - 1) g_nvalid = excl + cnt;
}

// ---------------- kernel 2: gather + quantize activations to e4m3 ----------------
__global__ void build_a_kernel(const float* __restrict__ outputs) {
    int m = blockIdx.x;
    int tid = threadIdx.x;
    if (tid == 0) {
        g_sumexp[m] = 0.f;
        g_sumlogit[m] = 0.f;
        g_tlogit[m] = 0.f;
    }
    int nv = g_nvalid;
    uint32_t* dst = (uint32_t*)(g_Aq + (size_t)m * D_DIM);
    if (m < nv) {
        const float* src = outputs + (size_t)g_valid_idx[m] * D_DIM;
        for (int i = tid; i < D_DIM / 4; i += blockDim.x) {
            float4 v = *(const float4*)(src + i * 4);
            dst[i] = pack4_e4m3(v.x * QA_SCALE, v.y * QA_SCALE,
                                v.z * QA_SCALE, v.w * QA_SCALE);
        }
    } else {
        for (int i = tid; i < D_DIM / 4; i += blockDim.x) dst[i] = 0u;
    }
}

// ---------------- kernel 3: W fp32 -> e4m3 (zero-pad to V_PAD) ----------------
__global__ void conv_w_kernel(const float* __restrict__ W) {
    long i = ((long)blockIdx.x * blockDim.x + threadIdx.x) * 4;
    const long nreal = (long)V_DIM * D_DIM;
    const long ntot  = (long)V_PAD * D_DIM;
    if (i < ntot) {
        uint32_t packed = 0u;
        if (i < nreal) {
            float4 v = *(const float4*)(W + i);
            packed = pack4_e4m3(v.x * QW_SCALE, v.y * QW_SCALE,
                                v.z * QW_SCALE, v.w * QW_SCALE);
        }
        *(uint32_t*)(g_Wq + i) = packed;
    }
}

// ---------------- epilogue helper (register-direct, lean) ----------------
template <bool CHK>
__device__ __forceinline__ void epilogue(float (&acc)[4][4][4], int m0w, int n0w,
                                         int nv, int lane) {
    #pragma unroll
    for (int i = 0; i < 4; i++) {
        int r0 = m0w + i * 16 + (lane >> 2);
        int r1 = r0 + 8;
        bool v0 = r0 < nv, v1 = r1 < nv;
        int tg0 = v0 ? g_tgt[r0] : -1;
        int tg1 = v1 ? g_tgt[r1] : -1;
        float se0 = 0.f, sr0 = 0.f, se1 = 0.f, sr1 = 0.f;
        #pragma unroll
        for (int g = 0; g < 4; g++) {
            int c0 = n0w + g * 8 + (lane & 3) * 2;
            float a0 = acc[i][g][0], a1 = acc[i][g][1];
            float a2 = acc[i][g][2], a3 = acc[i][g][3];
            if (!CHK || c0 < V_DIM) {
                se0 += ex2f(a0 * DEQ_L2E); sr0 += a0;
                se1 += ex2f(a2 * DEQ_L2E); sr1 += a2;
                if (c0 == tg0) g_tlogit[r0] = a0 * DEQ;
                if (c0 == tg1) g_tlogit[r1] = a2 * DEQ;
            }
            if (!CHK || c0 + 1 < V_DIM) {
                se0 += ex2f(a1 * DEQ_L2E); sr0 += a1;
                se1 += ex2f(a3 * DEQ_L2E); sr1 += a3;
                if (c0 + 1 == tg0) g_tlogit[r0] = a1 * DEQ;
                if (c0 + 1 == tg1) g_tlogit[r1] = a3 * DEQ;
            }
        }
        #pragma unroll
        for (int o = 1; o <= 2; o <<= 1) {
            se0 += __shfl_xor_sync(0xffffffffu, se0, o);
            sr0 += __shfl_xor_sync(0xffffffffu, sr0, o);
            se1 += __shfl_xor_sync(0xffffffffu, se1, o);
            sr1 += __shfl_xor_sync(0xffffffffu, sr1, o);
        }
        if ((lane & 3) == 0) {
            if (v0) {
                atomicAdd(&g_sumexp[r0], se0);
                atomicAdd(&g_sumlogit[r0], sr0 * DEQ);
            }
            if (v1) {
                atomicAdd(&g_sumexp[r1], se1);
                atomicAdd(&g_sumlogit[r1], sr1 * DEQ);
            }
        }
    }
}

// ---------------- kernel 4: FP8 QMMA, mbarrier producer/consumer ring ----------------
__global__ void __launch_bounds__(256, 2) gemm_epilogue_kernel() {
    extern __shared__ char smem[];
    uint32_t sb = smem_u32(smem);
    const uint32_t mbF = sb;           // full[s]  at sb + 8s   (count 256)
    const uint32_t mbE = sb + 32;      // empty[s] at sb+32+8s  (count 8)
    const uint32_t st0 = sb + SM_STAGE0;

    int nv = g_nvalid;
    int m0 = blockIdx.x * BM;
    if (m0 >= nv) return;
    int n0 = blockIdx.y * BN;

    int tid = threadIdx.x;
    int warp = tid >> 5, lane = tid & 31;
    int wm = warp & 1;        // A rows wm*64..+63
    int wn = warp >> 1;       // B rows wn*32..+31

    if (tid == 0) {
        #pragma unroll
        for (int s = 0; s < STAGES; s++) {
            MBAR_INIT(mbF + 8 * s, 256);
            MBAR_INIT(mbE + 8 * s, 8);
        }
    }
    __syncthreads();

    // cp.async slots: 4 A + 4 B 16B chunks per thread per stage
    uint32_t adst[4], aofs[4], bofs[4];
    const char* Ag = (const char*)g_Aq;
    const char* Wg = (const char*)g_Wq;
    #pragma unroll
    for (int i = 0; i < 4; i++) {
        int c = tid + i * 256;             // 1024 chunks = 128 rows x 8
        int r = c >> 3, cc = (c & 7) << 4;
        adst[i] = (uint32_t)(r * ROW_B + cc);
        aofs[i] = (uint32_t)((m0 + r) * D_DIM + cc);
        bofs[i] = (uint32_t)((n0 + r) * D_DIM + cc);
    }

    // ldmatrix base offsets (fragment layout validated R8-R11)
    uint32_t aoff = st0 +
        (uint32_t)(((lane & 7) + ((lane >> 3) & 1) * 8 + wm * 64) * ROW_B + (lane >> 4) * 16);
    uint32_t boff = st0 + MAT_STAGE +
        (uint32_t)(((lane & 7) + (lane >> 4) * 8 + wn * 32) * ROW_B + ((lane >> 3) & 1) * 16);

    float acc[4][4][4];
    #pragma unroll
    for (int i = 0; i < 4; i++)
        #pragma unroll
        for (int g = 0; g < 4; g++)
            #pragma unroll
            for (int q = 0; q < 4; q++)
                acc[i][g][q] = 0.f;

    // prologue: fill stages 0,1 (steps 0,1); no empty-wait needed (first fill)
    #pragma unroll
    for (int s = 0; s < 2; s++) {
        uint32_t ab = st0 + s * STAGE_BYTES;
        #pragma unroll
        for (int i = 0; i < 4; i++) {
            cp16(ab + adst[i], Ag + aofs[i] + s * BKB);
            cp16(ab + MAT_STAGE + adst[i], Wg + bofs[i] + s * BKB);
        }
        CP_ARRIVE_NOINC(mbF + 8 * s);
    }

    int ps = 2, pw = 0;    // producer stage / wrap count (parity = (pw&1)^1)
    int cs = 0, cw = 0;    // consumer stage / wrap count (parity = cw&1)

    for (int j = 0; j < KSTEPS; j++) {
        // ---- produce step j+2 ----
        if (j + 2 < KSTEPS) {
            MBAR_WAIT(mbE + 8 * ps, (uint32_t)((pw & 1) ^ 1));
            uint32_t ab = st0 + ps * STAGE_BYTES;
            uint32_t kb = (uint32_t)(j + 2) * BKB;
            #pragma unroll
            for (int i = 0; i < 4; i++) {
                cp16(ab + adst[i], Ag + aofs[i] + kb);
                cp16(ab + MAT_STAGE + adst[i], Wg + bofs[i] + kb);
            }
            CP_ARRIVE_NOINC(mbF + 8 * ps);
            if (++ps == STAGES) { ps = 0; pw++; }
        }

        // ---- consume step j ----
        MBAR_WAIT(mbF + 8 * cs, (uint32_t)(cw & 1));
        uint32_t sbase = (uint32_t)(cs * STAGE_BYTES);
        #pragma unroll
        for (int kk = 0; kk < 4; kk++) {        // 4 x k=32 sub-steps
            uint32_t af[4][4], bf[2][4];
            #pragma unroll
            for (int i = 0; i < 4; i++)
                LDSM_X4(af[i][0], af[i][1], af[i][2], af[i][3],
                        aoff + sbase + (uint32_t)(i * 16 * ROW_B + kk * 32));
            #pragma unroll
            for (int p = 0; p < 2; p++)
                LDSM_X4(bf[p][0], bf[p][1], bf[p][2], bf[p][3],
                        boff + sbase + (uint32_t)(p * 16 * ROW_B + kk * 32));
            #pragma unroll
            for (int i = 0; i < 4; i++)
                #pragma unroll
                for (int p = 0; p < 2; p++) {
                    MMA_FP8(acc[i][2 * p],     af[i], bf[p][0], bf[p][1]);
                    MMA_FP8(acc[i][2 * p + 1], af[i], bf[p][2], bf[p][3]);
                }
        }
        if (lane == 0) MBAR_ARRIVE(mbE + 8 * cs);
        if (++cs == STAGES) { cs = 0; cw++; }
    }

    // ---- register-direct epilogue ----
    int m0w = m0 + wm * 64;
    int n0w = n0 + wn * 32;
    if (n0 + BN <= V_DIM) epilogue<false>(acc, m0w, n0w, nv, lane);
    else                  epilogue<true >(acc, m0w, n0w, nv, lane);
}

// ---------------- kernel 5: final scalar reduction ----------------
__global__ void final_kernel(float* __restrict__ out) {
    __shared__ double s_n[32], s_s[32];
    int tid = threadIdx.x;
    int nv = g_nvalid;
    double nll = 0.0, slp = 0.0;
    for (int m = tid; m < nv; m += blockDim.x) {
        float lse = logf(g_sumexp[m]);
        nll += (double)lse - (double)g_tlogit[m];
        slp += (double)g_sumlogit[m] - (double)V_DIM * (double)lse;
    }
    #pragma unroll
    for (int o = 16; o; o >>= 1) {
        nll += __shfl_down_sync(0xffffffffu, nll, o);
        slp += __shfl_down_sync(0xffffffffu, slp, o);
    }
    if ((tid & 31) == 0) { s_n[tid >> 5] = nll; s_s[tid >> 5] = slp; }
    __syncthreads();
    if (tid < 32) {
        int nw = blockDim.x >> 5;
        nll = (tid < nw) ? s_n[tid] : 0.0;
        slp = (tid < nw) ? s_s[tid] : 0.0;
        #pragma unroll
        for (int o = 16; o; o >>= 1) {
            nll += __shfl_down_sync(0xffffffffu, nll, o);
            slp += __shfl_down_sync(0xffffffffu, slp, o);
        }
        if (tid == 0) {
            double n = (double)nv;
            double loss = 0.9 * (nll / n) - 0.1 * (slp / (n * (double)V_DIM));
            out[0] = (float)loss;
        }
    }
}

// ---------------- launch ----------------
extern "C" void kernel_launch(void* const* d_in, const int* in_sizes, int n_in,
                              void* d_out, int out_size) {
    const int*           targets = (const int*)d_in[0];
    const unsigned char* masks   = (const unsigned char*)d_in[1];
    const float*         outputs = (const float*)d_in[2];
    const float*         W       = (const float*)d_in[3];
    int n_tokens = in_sizes[0];   // 4096

    static int s_attr_done = 0;
    if (!s_attr_done) {
        cudaFuncSetAttribute(gemm_epilogue_kernel,
                             cudaFuncAttributeMaxDynamicSharedMemorySize, SMEM_TOTAL);
        s_attr_done = 1;
    }

    gather_kernel<<<1, 1024>>>(targets, masks, n_tokens);
    build_a_kernel<<<n_tokens, 256>>>(outputs);

    long ntot = (long)V_PAD * D_DIM;
    int conv_blocks = (int)((ntot / 4 + 255) / 256);
    conv_w_kernel<<<conv_blocks, 256>>>(W);

    dim3 grid((TOKENS_MAX + BM - 1) / BM, N_TILES);
    gemm_epilogue_kernel<<<grid, 256, SMEM_TOTAL>>>();

    final_kernel<<<1, 1024>>>((float*)d_out);
}

// round 13
// speedup vs baseline: 1.0366x; 1.0366x over previous
#include <cuda_runtime.h>
#include <cuda_bf16.h>
#include <cuda_fp16.h>
#include <math.h>
#include <stdint.h>

#define TOKENS_MAX 4096
#define D_DIM 1024
#define V_DIM 50257
#define BM 128
#define BN 256
#define BKB 64                        // K elems (e4m3 bytes) per stage
#define N_TILES 197                   // ceil(50257/256)
#define V_PAD (N_TILES * BN)          // 50432
#define KSTEPS (D_DIM / BKB)          // 16
#define STAGES 3
#define ROW_B 80                      // padded stage row bytes (64 data + 16)
#define A_STAGE (BM * ROW_B)          // 10240
#define B_STAGE (BN * ROW_B)          // 20480
#define STAGE_BYTES (A_STAGE + B_STAGE) // 30720
#define SMEM_TOTAL (STAGES * STAGE_BYTES) // 92160 -> 2 CTAs/SM

#define QA_SCALE 16.0f
#define QW_SCALE 64.0f
#define DEQ (1.0f / (QA_SCALE * QW_SCALE))     // 1/1024
#define DEQ_L2E (DEQ * 1.4426950408889634f)

// ---------------- device-global scratch ----------------
__device__ __align__(128) int8_t g_Wq[(size_t)V_PAD * D_DIM];
__device__ __align__(128) int8_t g_Aq[(size_t)TOKENS_MAX * D_DIM];
__device__ int   g_valid_idx[TOKENS_MAX];
__device__ int   g_tgt[TOKENS_MAX];
__device__ int   g_nvalid;
__device__ float g_sumexp[TOKENS_MAX];
__device__ float g_sumlogit[TOKENS_MAX];
__device__ float g_tlogit[TOKENS_MAX];

__device__ __forceinline__ uint32_t smem_u32(const void* p) {
    uint32_t a;
    asm("{ .reg .u64 t; cvta.to.shared.u64 t, %1; cvt.u32.u64 %0, t; }" : "=r"(a) : "l"(p));
    return a;
}
__device__ __forceinline__ void cp16(uint32_t dst, const void* src) {
    asm volatile("cp.async.cg.shared.global [%0], [%1], 16;\n" :: "r"(dst), "l"(src));
}
__device__ __forceinline__ float ex2f(float x) {
    float r;
    asm("ex2.approx.f32 %0, %1;" : "=f"(r) : "f"(x));
    return r;
}
__device__ __forceinline__ uint16_t f2e4m3x2(float hi, float lo) {
    uint16_t r;
    asm("cvt.rn.satfinite.e4m3x2.f32 %0, %1, %2;" : "=h"(r) : "f"(hi), "f"(lo));
    return r;
}
__device__ __forceinline__ uint32_t pack4_e4m3(float x0, float x1, float x2, float x3) {
    uint32_t lo = f2e4m3x2(x1, x0);
    uint32_t hi = f2e4m3x2(x3, x2);
    return lo | (hi << 16);
}
#define LDSM_X4(R0, R1, R2, R3, addr)                                          \
    asm volatile("ldmatrix.sync.aligned.m8n8.x4.shared.b16 {%0,%1,%2,%3}, [%4];" \
                 : "=r"(R0), "=r"(R1), "=r"(R2), "=r"(R3) : "r"(addr))
// fp8 MMA with f16 accumulators (2 regs)
#define MMA_FP8H(d, a, b0, b1)                                                 \
    asm volatile("mma.sync.aligned.m16n8k32.row.col.f16.e4m3.e4m3.f16 "        \
                 "{%0,%1}, {%2,%3,%4,%5}, {%6,%7}, {%0,%1};"                   \
                 : "+r"((d)[0]), "+r"((d)[1])                                  \
                 : "r"((a)[0]), "r"((a)[1]), "r"((a)[2]), "r"((a)[3]),         \
                   "r"(b0), "r"(b1))

// ---------------- kernel 1: mask-dtype detect + compact valid tokens ----------------
__global__ void gather_kernel(const int* __restrict__ targets,
                              const unsigned char* __restrict__ masks_raw,
                              int n_tokens) {
    __shared__ int s_isu8;
    __shared__ int wsum[32];
    int tid = threadIdx.x;
    if (tid == 0) s_isu8 = 0;
    __syncthreads();

    int flag = 0;
    for (int i = tid; i < n_tokens; i += blockDim.x)
        if ((i & 3) != 0 && masks_raw[i] != 0) flag = 1;
    if (flag) atomicOr(&s_isu8, 1);
    __syncthreads();
    const bool isu8 = (s_isu8 != 0);
    const int* masks_i32 = (const int*)masks_raw;

    int C = (n_tokens + blockDim.x - 1) / blockDim.x;
    int start = tid * C;
    int end = min(start + C, n_tokens);
    int cnt = 0;
    for (int i = start; i < end; i++)
        cnt += isu8 ? (masks_raw[i] != 0) : (masks_i32[i] != 0);

    int lane = tid & 31, wid = tid >> 5;
    int v = cnt;
    #pragma unroll
    for (int o = 1; o < 32; o <<= 1) {
        int t = __shfl_up_sync(0xffffffffu, v, o);
        if (lane >= o) v += t;
    }
    if (lane == 31) wsum[wid] = v;
    __syncthreads();
    if (wid == 0) {
        int nw = blockDim.x >> 5;
        int w = (lane < nw) ? wsum[lane] : 0;
        #pragma unroll
        for (int o = 1; o < 32; o <<= 1) {
            int t = __shfl_up_sync(0xffffffffu, w, o);
            if (lane >= o) w += t;
        }
        wsum[lane] = w;
    }
    __syncthreads();
    int excl = v - cnt + (wid > 0 ? wsum[wid - 1] : 0);

    int off = excl;
    for (int i = start; i < end; i++) {
        bool mk = isu8 ? (masks_raw[i] != 0) : (masks_i32[i] != 0);
        if (mk) {
            g_valid_idx[off] = i;
            g_tgt[off] = targets[i];
            off++;
        }
    }
    if (tid == blockDim.x - 1) g_nvalid = excl + cnt;
}

// ---------------- kernel 2: gather + quantize activations to e4m3 ----------------
__global__ void build_a_kernel(const float* __restrict__ outputs) {
    int m = blockIdx.x;
    int tid = threadIdx.x;
    if (tid == 0) {
        g_sumexp[m] = 0.f;
        g_sumlogit[m] = 0.f;
        g_tlogit[m] = 0.f;
    }
    int nv = g_nvalid;
    uint32_t* dst = (uint32_t*)(g_Aq + (size_t)m * D_DIM);
    if (m < nv) {
        const float* src = outputs + (size_t)g_valid_idx[m] * D_DIM;
        for (int i = tid; i < D_DIM / 4; i += blockDim.x) {
            float4 v = *(const float4*)(src + i * 4);
            dst[i] = pack4_e4m3(v.x * QA_SCALE, v.y * QA_SCALE,
                                v.z * QA_SCALE, v.w * QA_SCALE);
        }
    } else {
        for (int i = tid; i < D_DIM / 4; i += blockDim.x) dst[i] = 0u;
    }
}

// ---------------- kernel 3: W fp32 -> e4m3 (zero-pad to V_PAD) ----------------
__global__ void conv_w_kernel(const float* __restrict__ W) {
    long i = ((long)blockIdx.x * blockDim.x + threadIdx.x) * 4;
    const long nreal = (long)V_DIM * D_DIM;
    const long ntot  = (long)V_PAD * D_DIM;
    if (i < ntot) {
        uint32_t packed = 0u;
        if (i < nreal) {
            float4 v = *(const float4*)(W + i);
            packed = pack4_e4m3(v.x * QW_SCALE, v.y * QW_SCALE,
                                v.z * QW_SCALE, v.w * QW_SCALE);
        }
        *(uint32_t*)(g_Wq + i) = packed;
    }
}

// ---------------- epilogue helper (register-direct, f16 acc unpack) ----------------
template <bool CHK>
__device__ __forceinline__ void epilogue(uint32_t (&acc)[4][8][2], int m0w, int n0w,
                                         int nv, int lane) {
    #pragma unroll
    for (int i = 0; i < 4; i++) {
        int r0 = m0w + i * 16 + (lane >> 2);
        int r1 = r0 + 8;
        bool v0 = r0 < nv, v1 = r1 < nv;
        int tg0 = v0 ? g_tgt[r0] : -1;
        int tg1 = v1 ? g_tgt[r1] : -1;
        float se0 = 0.f, sr0 = 0.f, se1 = 0.f, sr1 = 0.f;
        #pragma unroll
        for (int g = 0; g < 8; g++) {
            int c0 = n0w + g * 8 + (lane & 3) * 2;
            float2 p0 = __half22float2(*(const __half2*)&acc[i][g][0]);  // row r0: c0, c0+1
            float2 p1 = __half22float2(*(const __half2*)&acc[i][g][1]);  // row r1: c0, c0+1
            if (!CHK || c0 < V_DIM) {
                se0 += ex2f(p0.x * DEQ_L2E); sr0 += p0.x;
                se1 += ex2f(p1.x * DEQ_L2E); sr1 += p1.x;
                if (c0 == tg0) g_tlogit[r0] = p0.x * DEQ;
                if (c0 == tg1) g_tlogit[r1] = p1.x * DEQ;
            }
            if (!CHK || c0 + 1 < V_DIM) {
                se0 += ex2f(p0.y * DEQ_L2E); sr0 += p0.y;
                se1 += ex2f(p1.y * DEQ_L2E); sr1 += p1.y;
                if (c0 + 1 == tg0) g_tlogit[r0] = p0.y * DEQ;
                if (c0 + 1 == tg1) g_tlogit[r1] = p1.y * DEQ;
            }
        }
        #pragma unroll
        for (int o = 1; o <= 2; o <<= 1) {
            se0 += __shfl_xor_sync(0xffffffffu, se0, o);
            sr0 += __shfl_xor_sync(0xffffffffu, sr0, o);
            se1 += __shfl_xor_sync(0xffffffffu, se1, o);
            sr1 += __shfl_xor_sync(0xffffffffu, sr1, o);
        }
        if ((lane & 3) == 0) {
            if (v0) {
                atomicAdd(&g_sumexp[r0], se0);
                atomicAdd(&g_sumlogit[r0], sr0 * DEQ);
            }
            if (v1) {
                atomicAdd(&g_sumexp[r1], se1);
                atomicAdd(&g_sumlogit[r1], sr1 * DEQ);
            }
        }
    }
}

// ---------------- kernel 4: 128x256 FP8 QMMA (f16 acc), warp tile 64x64, 2 CTAs/SM ----------------
__global__ void __launch_bounds__(256, 2) gemm_epilogue_kernel() {
    extern __shared__ char smem[];
    uint32_t sb = smem_u32(smem);

    int nv = g_nvalid;
    int m0 = blockIdx.x * BM;
    if (m0 >= nv) return;
    int n0 = blockIdx.y * BN;

    int tid = threadIdx.x;
    int warp = tid >> 5, lane = tid & 31;
    int wm = warp & 1;        // A rows wm*64..+63
    int wn = warp >> 1;       // B rows wn*64..+63 (4 n-slices of 64)

    // cp.async slots per stage: A 2 chunks, B 4 chunks per thread (16B each)
    uint32_t adst[2], aofs[2], bdst[4], bofs[4];
    const char* Ag = (const char*)g_Aq;
    const char* Wg = (const char*)g_Wq;
    #pragma unroll
    for (int i = 0; i < 2; i++) {
        int c = tid + i * 256;             // 512 chunks = 128 rows x 4
        int r = c >> 2, cc = (c & 3) << 4;
        adst[i] = (uint32_t)(r * ROW_B + cc);
        aofs[i] = (uint32_t)((m0 + r) * D_DIM + cc);
    }
    #pragma unroll
    for (int i = 0; i < 4; i++) {
        int c = tid + i * 256;             // 1024 chunks = 256 rows x 4
        int r = c >> 2, cc = (c & 3) << 4;
        bdst[i] = (uint32_t)(r * ROW_B + cc);
        bofs[i] = (uint32_t)((n0 + r) * D_DIM + cc);
    }

    // ldmatrix base offsets (fragment layout validated R8-R12; row stride 80B bank-clean)
    uint32_t aoff = sb +
        (uint32_t)(((lane & 7) + ((lane >> 3) & 1) * 8 + wm * 64) * ROW_B + (lane >> 4) * 16);
    uint32_t boff = sb + A_STAGE +
        (uint32_t)(((lane & 7) + (lane >> 4) * 8 + wn * 64) * ROW_B + ((lane >> 3) & 1) * 16);

    uint32_t acc[4][8][2];
    #pragma unroll
    for (int i = 0; i < 4; i++)
        #pragma unroll
        for (int g = 0; g < 8; g++) {
            acc[i][g][0] = 0u;
            acc[i][g][1] = 0u;
        }

    // prologue: 2 stages in flight
    #pragma unroll
    for (int s = 0; s < 2; s++) {
        uint32_t ab = sb + s * STAGE_BYTES;
        uint32_t kb = (uint32_t)s * BKB;
        #pragma unroll
        for (int i = 0; i < 2; i++) cp16(ab + adst[i], Ag + aofs[i] + kb);
        #pragma unroll
        for (int i = 0; i < 4; i++) cp16(ab + A_STAGE + bdst[i], Wg + bofs[i] + kb);
        asm volatile("cp.async.commit_group;" ::: "memory");
    }

    for (int j = 0; j < KSTEPS; j++) {
        asm volatile("cp.async.wait_group 1;" ::: "memory");
        __syncthreads();   // one barrier per K-step (16 total)

        if (j + 2 < KSTEPS) {
            int s = (j + 2) % STAGES;
            uint32_t ab = sb + s * STAGE_BYTES;
            uint32_t kb = (uint32_t)(j + 2) * BKB;
            #pragma unroll
            for (int i = 0; i < 2; i++) cp16(ab + adst[i], Ag + aofs[i] + kb);
            #pragma unroll
            for (int i = 0; i < 4; i++) cp16(ab + A_STAGE + bdst[i], Wg + bofs[i] + kb);
        }
        asm volatile("cp.async.commit_group;" ::: "memory");

        uint32_t sbase = (uint32_t)((j % STAGES) * STAGE_BYTES);
        #pragma unroll
        for (int kk = 0; kk < 2; kk++) {        // 2 x k=32 sub-steps
            uint32_t af[4][4], bf[4][4];
            #pragma unroll
            for (int i = 0; i < 4; i++)
                LDSM_X4(af[i][0], af[i][1], af[i][2], af[i][3],
                        aoff + sbase + (uint32_t)(i * 16 * ROW_B + kk * 32));
            #pragma unroll
            for (int p = 0; p < 4; p++)
                LDSM_X4(bf[p][0], bf[p][1], bf[p][2], bf[p][3],
                        boff + sbase + (uint32_t)(p * 16 * ROW_B + kk * 32));
            #pragma unroll
            for (int i = 0; i < 4; i++)
                #pragma unroll
                for (int p = 0; p < 4; p++) {
                    MMA_FP8H(acc[i][2 * p],     af[i], bf[p][0], bf[p][1]);
                    MMA_FP8H(acc[i][2 * p + 1], af[i], bf[p][2], bf[p][3]);
                }
        }
    }

    // ---- register-direct epilogue ----
    int m0w = m0 + wm * 64;
    int n0w = n0 + wn * 64;
    if (n0 + BN <= V_DIM) epilogue<false>(acc, m0w, n0w, nv, lane);
    else                  epilogue<true >(acc, m0w, n0w, nv, lane);
}

// ---------------- kernel 5: final scalar reduction ----------------
__global__ void final_kernel(float* __restrict__ out) {
    __shared__ double s_n[32], s_s[32];
    int tid = threadIdx.x;
    int nv = g_nvalid;
    double nll = 0.0, slp = 0.0;
    for (int m = tid; m < nv; m += blockDim.x) {
        float lse = logf(g_sumexp[m]);
        nll += (double)lse - (double)g_tlogit[m];
        slp += (double)g_sumlogit[m] - (double)V_DIM * (double)lse;
    }
    #pragma unroll
    for (int o = 16; o; o >>= 1) {
        nll += __shfl_down_sync(0xffffffffu, nll, o);
        slp += __shfl_down_sync(0xffffffffu, slp, o);
    }
    if ((tid & 31) == 0) { s_n[tid >> 5] = nll; s_s[tid >> 5] = slp; }
    __syncthreads();
    if (tid < 32) {
        int nw = blockDim.x >> 5;
        nll = (tid < nw) ? s_n[tid] : 0.0;
        slp = (tid < nw) ? s_s[tid] : 0.0;
        #pragma unroll
        for (int o = 16; o; o >>= 1) {
            nll += __shfl_down_sync(0xffffffffu, nll, o);
            slp += __shfl_down_sync(0xffffffffu, slp, o);
        }
        if (tid == 0) {
            double n = (double)nv;
            double loss = 0.9 * (nll / n) - 0.1 * (slp / (n * (double)V_DIM));
            out[0] = (float)loss;
        }
    }
}

// ---------------- launch ----------------
extern "C" void kernel_launch(void* const* d_in, const int* in_sizes, int n_in,
                              void* d_out, int out_size) {
    const int*           targets = (const int*)d_in[0];
    const unsigned char* masks   = (const unsigned char*)d_in[1];
    const float*         outputs = (const float*)d_in[2];
    const float*         W       = (const float*)d_in[3];
    int n_tokens = in_sizes[0];   // 4096

    static int s_attr_done = 0;
    if (!s_attr_done) {
        cudaFuncSetAttribute(gemm_epilogue_kernel,
                             cudaFuncAttributeMaxDynamicSharedMemorySize, SMEM_TOTAL);
        s_attr_done = 1;
    }

    gather_kernel<<<1, 1024>>>(targets, masks, n_tokens);
    build_a_kernel<<<n_tokens, 256>>>(outputs);

    long ntot = (long)V_PAD * D_DIM;
    int conv_blocks = (int)((ntot / 4 + 255) / 256);
    conv_w_kernel<<<conv_blocks, 256>>>(W);

    dim3 grid((TOKENS_MAX + BM - 1) / BM, N_TILES);
    gemm_epilogue_kernel<<<grid, 256, SMEM_TOTAL>>>();

    final_kernel<<<1, 1024>>>((float*)d_out);
}

// round 14
// speedup vs baseline: 1.0663x; 1.0286x over previous
#include <cuda_runtime.h>
#include <cuda_bf16.h>
#include <cuda_fp16.h>
#include <math.h>
#include <stdint.h>

#define TOKENS_MAX 4096
#define D_DIM 1024
#define V_DIM 50257
#define BM 128
#define BN 256
#define BKB 64                        // K elems (e4m3 bytes) per stage
#define N_TILES 197                   // ceil(50257/256)
#define V_PAD (N_TILES * BN)          // 50432
#define KSTEPS (D_DIM / BKB)          // 16
#define STAGES 3
#define ROW_B 80                      // padded stage row bytes (64 data + 16)
#define A_STAGE (BM * ROW_B)          // 10240
#define B_STAGE (BN * ROW_B)          // 20480
#define STAGE_BYTES (A_STAGE + B_STAGE) // 30720
#define SMEM_TOTAL (STAGES * STAGE_BYTES) // 92160 -> 2 CTAs/SM

#define QA_SCALE 16.0f
#define QW_SCALE 64.0f
#define DEQ (1.0f / (QA_SCALE * QW_SCALE))     // 1/1024
#define DEQ_L2E (DEQ * 1.4426950408889634f)

// ---------------- device-global scratch ----------------
__device__ __align__(128) int8_t g_Wq[(size_t)V_PAD * D_DIM];
__device__ __align__(128) int8_t g_Aq[(size_t)TOKENS_MAX * D_DIM];
__device__ int   g_valid_idx[TOKENS_MAX];
__device__ int   g_tgt[TOKENS_MAX];
__device__ int   g_nvalid;
__device__ float g_sumexp[TOKENS_MAX];
__device__ float g_sumlogit[TOKENS_MAX];
__device__ float g_tlogit[TOKENS_MAX];

__device__ __forceinline__ uint32_t smem_u32(const void* p) {
    uint32_t a;
    asm("{ .reg .u64 t; cvta.to.shared.u64 t, %1; cvt.u32.u64 %0, t; }" : "=r"(a) : "l"(p));
    return a;
}
__device__ __forceinline__ void cp16(uint32_t dst, const void* src) {
    asm volatile("cp.async.cg.shared.global [%0], [%1], 16;\n" :: "r"(dst), "l"(src));
}
__device__ __forceinline__ float ex2f(float x) {
    float r;
    asm("ex2.approx.f32 %0, %1;" : "=f"(r) : "f"(x));
    return r;
}
__device__ __forceinline__ __half2 h2ex2(__half2 x) {
    uint32_t r, xi = *(const uint32_t*)&x;
    asm("ex2.approx.f16x2 %0, %1;" : "=r"(r) : "r"(xi));
    return *(__half2*)&r;
}
__device__ __forceinline__ uint16_t f2e4m3x2(float hi, float lo) {
    uint16_t r;
    asm("cvt.rn.satfinite.e4m3x2.f32 %0, %1, %2;" : "=h"(r) : "f"(hi), "f"(lo));
    return r;
}
__device__ __forceinline__ uint32_t pack4_e4m3(float x0, float x1, float x2, float x3) {
    uint32_t lo = f2e4m3x2(x1, x0);
    uint32_t hi = f2e4m3x2(x3, x2);
    return lo | (hi << 16);
}
#define LDSM_X4(R0, R1, R2, R3, addr)                                          \
    asm volatile("ldmatrix.sync.aligned.m8n8.x4.shared.b16 {%0,%1,%2,%3}, [%4];" \
                 : "=r"(R0), "=r"(R1), "=r"(R2), "=r"(R3) : "r"(addr))
// fp8 MMA with f16 accumulators (2 regs)
#define MMA_FP8H(d, a, b0, b1)                                                 \
    asm volatile("mma.sync.aligned.m16n8k32.row.col.f16.e4m3.e4m3.f16 "        \
                 "{%0,%1}, {%2,%3,%4,%5}, {%6,%7}, {%0,%1};"                   \
                 : "+r"((d)[0]), "+r"((d)[1])                                  \
                 : "r"((a)[0]), "r"((a)[1]), "r"((a)[2]), "r"((a)[3]),         \
                   "r"(b0), "r"(b1))

// ---------------- kernel 1: mask-dtype detect + compact valid tokens ----------------
__global__ void gather_kernel(const int* __restrict__ targets,
                              const unsigned char* __restrict__ masks_raw,
                              int n_tokens) {
    __shared__ int s_isu8;
    __shared__ int wsum[32];
    int tid = threadIdx.x;
    if (tid == 0) s_isu8 = 0;
    __syncthreads();

    int flag = 0;
    for (int i = tid; i < n_tokens; i += blockDim.x)
        if ((i & 3) != 0 && masks_raw[i] != 0) flag = 1;
    if (flag) atomicOr(&s_isu8, 1);
    __syncthreads();
    const bool isu8 = (s_isu8 != 0);
    const int* masks_i32 = (const int*)masks_raw;

    int C = (n_tokens + blockDim.x - 1) / blockDim.x;
    int start = tid * C;
    int end = min(start + C, n_tokens);
    int cnt = 0;
    for (int i = start; i < end; i++)
        cnt += isu8 ? (masks_raw[i] != 0) : (masks_i32[i] != 0);

    int lane = tid & 31, wid = tid >> 5;
    int v = cnt;
    #pragma unroll
    for (int o = 1; o < 32; o <<= 1) {
        int t = __shfl_up_sync(0xffffffffu, v, o);
        if (lane >= o) v += t;
    }
    if (lane == 31) wsum[wid] = v;
    __syncthreads();
    if (wid == 0) {
        int nw = blockDim.x >> 5;
        int w = (lane < nw) ? wsum[lane] : 0;
        #pragma unroll
        for (int o = 1; o < 32; o <<= 1) {
            int t = __shfl_up_sync(0xffffffffu, w, o);
            if (lane >= o) w += t;
        }
        wsum[lane] = w;
    }
    __syncthreads();
    int excl = v - cnt + (wid > 0 ? wsum[wid - 1] : 0);

    int off = excl;
    for (int i = start; i < end; i++) {
        bool mk = isu8 ? (masks_raw[i] != 0) : (masks_i32[i] != 0);
        if (mk) {
            g_valid_idx[off] = i;
            g_tgt[off] = targets[i];
            off++;
        }
    }
    if (tid == blockDim.x - 1) g_nvalid = excl + cnt;
}

// ---------------- kernel 2: gather + quantize activations to e4m3 ----------------
__global__ void build_a_kernel(const float* __restrict__ outputs) {
    int m = blockIdx.x;
    int tid = threadIdx.x;
    if (tid == 0) {
        g_sumexp[m] = 0.f;
        g_sumlogit[m] = 0.f;
    }
    int nv = g_nvalid;
    uint32_t* dst = (uint32_t*)(g_Aq + (size_t)m * D_DIM);
    if (m < nv) {
        const float* src = outputs + (size_t)g_valid_idx[m] * D_DIM;
        for (int i = tid; i < D_DIM / 4; i += blockDim.x) {
            float4 v = *(const float4*)(src + i * 4);
            dst[i] = pack4_e4m3(v.x * QA_SCALE, v.y * QA_SCALE,
                                v.z * QA_SCALE, v.w * QA_SCALE);
        }
    } else {
        for (int i = tid; i < D_DIM / 4; i += blockDim.x) dst[i] = 0u;
    }
}

// ---------------- kernel 2b: exact target logits (fp32 dot) ----------------
__global__ void tlogit_kernel(const float* __restrict__ outputs,
                              const float* __restrict__ W) {
    __shared__ float ws[4];
    int m = blockIdx.x;
    if (m >= g_nvalid) return;
    int tid = threadIdx.x;               // 128 threads
    int lane = tid & 31, wid = tid >> 5;
    const float* arow = outputs + (size_t)g_valid_idx[m] * D_DIM;
    const float* wrow = W + (size_t)g_tgt[m] * D_DIM;
    int i = tid * 8;                      // 128 threads x 8 elems = 1024
    float4 a0 = *(const float4*)(arow + i);
    float4 a1 = *(const float4*)(arow + i + 4);
    float4 w0 = *(const float4*)(wrow + i);
    float4 w1 = *(const float4*)(wrow + i + 4);
    float s = a0.x * w0.x + a0.y * w0.y + a0.z * w0.z + a0.w * w0.w
            + a1.x * w1.x + a1.y * w1.y + a1.z * w1.z + a1.w * w1.w;
    #pragma unroll
    for (int o = 16; o; o >>= 1) s += __shfl_down_sync(0xffffffffu, s, o);
    if (lane == 0) ws[wid] = s;
    __syncthreads();
    if (tid == 0) g_tlogit[m] = ws[0] + ws[1] + ws[2] + ws[3];
}

// ---------------- kernel 3: W fp32 -> e4m3 (zero-pad to V_PAD) ----------------
__global__ void conv_w_kernel(const float* __restrict__ W) {
    long i = ((long)blockIdx.x * blockDim.x + threadIdx.x) * 4;
    const long nreal = (long)V_DIM * D_DIM;
    const long ntot  = (long)V_PAD * D_DIM;
    if (i < ntot) {
        uint32_t packed = 0u;
        if (i < nreal) {
            float4 v = *(const float4*)(W + i);
            packed = pack4_e4m3(v.x * QW_SCALE, v.y * QW_SCALE,
                                v.z * QW_SCALE, v.w * QW_SCALE);
        }
        *(uint32_t*)(g_Wq + i) = packed;
    }
}

// ---------------- epilogue helper (half2 fast path, no target logic) ----------------
template <bool CHK>
__device__ __forceinline__ void epilogue(uint32_t (&acc)[4][8][2], int m0w, int n0w,
                                         int nv, int lane) {
    const __half2 dq = __float2half2_rn(DEQ_L2E);
    #pragma unroll
    for (int i = 0; i < 4; i++) {
        int r0 = m0w + i * 16 + (lane >> 2);
        int r1 = r0 + 8;
        float se0, sr0, se1, sr1;
        if (!CHK) {
            __half2 hse0 = __float2half2_rn(0.f);
            __half2 hsr0 = hse0, hse1 = hse0, hsr1 = hse0;
            #pragma unroll
            for (int g = 0; g < 8; g++) {
                __half2 a0 = *(const __half2*)&acc[i][g][0];
                __half2 a1 = *(const __half2*)&acc[i][g][1];
                hse0 = __hadd2(hse0, h2ex2(__hmul2(a0, dq)));
                hsr0 = __hadd2(hsr0, a0);
                hse1 = __hadd2(hse1, h2ex2(__hmul2(a1, dq)));
                hsr1 = __hadd2(hsr1, a1);
            }
            float2 f;
            f = __half22float2(hse0); se0 = f.x + f.y;
            f = __half22float2(hsr0); sr0 = f.x + f.y;
            f = __half22float2(hse1); se1 = f.x + f.y;
            f = __half22float2(hsr1); sr1 = f.x + f.y;
        } else {
            se0 = sr0 = se1 = sr1 = 0.f;
            #pragma unroll
            for (int g = 0; g < 8; g++) {
                int c0 = n0w + g * 8 + (lane & 3) * 2;
                float2 p0 = __half22float2(*(const __half2*)&acc[i][g][0]);
                float2 p1 = __half22float2(*(const __half2*)&acc[i][g][1]);
                if (c0 < V_DIM) {
                    se0 += ex2f(p0.x * DEQ_L2E); sr0 += p0.x;
                    se1 += ex2f(p1.x * DEQ_L2E); sr1 += p1.x;
                }
                if (c0 + 1 < V_DIM) {
                    se0 += ex2f(p0.y * DEQ_L2E); sr0 += p0.y;
                    se1 += ex2f(p1.y * DEQ_L2E); sr1 += p1.y;
                }
            }
        }
        #pragma unroll
        for (int o = 1; o <= 2; o <<= 1) {
            se0 += __shfl_xor_sync(0xffffffffu, se0, o);
            sr0 += __shfl_xor_sync(0xffffffffu, sr0, o);
            se1 += __shfl_xor_sync(0xffffffffu, se1, o);
            sr1 += __shfl_xor_sync(0xffffffffu, sr1, o);
        }
        if ((lane & 3) == 0) {
            if (r0 < nv) {
                atomicAdd(&g_sumexp[r0], se0);
                atomicAdd(&g_sumlogit[r0], sr0 * DEQ);
            }
            if (r1 < nv) {
                atomicAdd(&g_sumexp[r1], se1);
                atomicAdd(&g_sumlogit[r1], sr1 * DEQ);
            }
        }
    }
}

// ---------------- kernel 4: 128x256 FP8 QMMA (f16 acc), warp tile 64x64, 2 CTAs/SM ----------------
__global__ void __launch_bounds__(256, 2) gemm_epilogue_kernel() {
    extern __shared__ char smem[];
    uint32_t sb = smem_u32(smem);

    int nv = g_nvalid;
    int m0 = blockIdx.x * BM;
    if (m0 >= nv) return;
    int n0 = blockIdx.y * BN;

    int tid = threadIdx.x;
    int warp = tid >> 5, lane = tid & 31;
    int wm = warp & 1;        // A rows wm*64..+63
    int wn = warp >> 1;       // B rows wn*64..+63 (4 n-slices of 64)

    // cp.async slots per stage: A 2 chunks, B 4 chunks per thread (16B each)
    uint32_t adst[2], aofs[2], bdst[4], bofs[4];
    const char* Ag = (const char*)g_Aq;
    const char* Wg = (const char*)g_Wq;
    #pragma unroll
    for (int i = 0; i < 2; i++) {
        int c = tid + i * 256;             // 512 chunks = 128 rows x 4
        int r = c >> 2, cc = (c & 3) << 4;
        adst[i] = (uint32_t)(r * ROW_B + cc);
        aofs[i] = (uint32_t)((m0 + r) * D_DIM + cc);
    }
    #pragma unroll
    for (int i = 0; i < 4; i++) {
        int c = tid + i * 256;             // 1024 chunks = 256 rows x 4
        int r = c >> 2, cc = (c & 3) << 4;
        bdst[i] = (uint32_t)(r * ROW_B + cc);
        bofs[i] = (uint32_t)((n0 + r) * D_DIM + cc);
    }

    // ldmatrix base offsets (fragment layout validated R8-R13)
    uint32_t aoff = sb +
        (uint32_t)(((lane & 7) + ((lane >> 3) & 1) * 8 + wm * 64) * ROW_B + (lane >> 4) * 16);
    uint32_t boff = sb + A_STAGE +
        (uint32_t)(((lane & 7) + (lane >> 4) * 8 + wn * 64) * ROW_B + ((lane >> 3) & 1) * 16);

    uint32_t acc[4][8][2];
    #pragma unroll
    for (int i = 0; i < 4; i++)
        #pragma unroll
        for (int g = 0; g < 8; g++) {
            acc[i][g][0] = 0u;
            acc[i][g][1] = 0u;
        }

    // prologue: 2 stages in flight
    #pragma unroll
    for (int s = 0; s < 2; s++) {
        uint32_t ab = sb + s * STAGE_BYTES;
        uint32_t kb = (uint32_t)s * BKB;
        #pragma unroll
        for (int i = 0; i < 2; i++) cp16(ab + adst[i], Ag + aofs[i] + kb);
        #pragma unroll
        for (int i = 0; i < 4; i++) cp16(ab + A_STAGE + bdst[i], Wg + bofs[i] + kb);
        asm volatile("cp.async.commit_group;" ::: "memory");
    }

    for (int j = 0; j < KSTEPS; j++) {
        asm volatile("cp.async.wait_group 1;" ::: "memory");
        __syncthreads();   // one barrier per K-step (16 total)

        if (j + 2 < KSTEPS) {
            int s = (j + 2) % STAGES;
            uint32_t ab = sb + s * STAGE_BYTES;
            uint32_t kb = (uint32_t)(j + 2) * BKB;
            #pragma unroll
            for (int i = 0; i < 2; i++) cp16(ab + adst[i], Ag + aofs[i] + kb);
            #pragma unroll
            for (int i = 0; i < 4; i++) cp16(ab + A_STAGE + bdst[i], Wg + bofs[i] + kb);
        }
        asm volatile("cp.async.commit_group;" ::: "memory");

        uint32_t sbase = (uint32_t)((j % STAGES) * STAGE_BYTES);
        #pragma unroll
        for (int kk = 0; kk < 2; kk++) {        // 2 x k=32 sub-steps
            uint32_t af[4][4], bf[4][4];
            #pragma unroll
            for (int i = 0; i < 4; i++)
                LDSM_X4(af[i][0], af[i][1], af[i][2], af[i][3],
                        aoff + sbase + (uint32_t)(i * 16 * ROW_B + kk * 32));
            #pragma unroll
            for (int p = 0; p < 4; p++)
                LDSM_X4(bf[p][0], bf[p][1], bf[p][2], bf[p][3],
                        boff + sbase + (uint32_t)(p * 16 * ROW_B + kk * 32));
            #pragma unroll
            for (int i = 0; i < 4; i++)
                #pragma unroll
                for (int p = 0; p < 4; p++) {
                    MMA_FP8H(acc[i][2 * p],     af[i], bf[p][0], bf[p][1]);
                    MMA_FP8H(acc[i][2 * p + 1], af[i], bf[p][2], bf[p][3]);
                }
        }
    }

    // ---- register-direct epilogue ----
    int m0w = m0 + wm * 64;
    int n0w = n0 + wn * 64;
    if (n0 + BN <= V_DIM) epilogue<false>(acc, m0w, n0w, nv, lane);
    else                  epilogue<true >(acc, m0w, n0w, nv, lane);
}

// ---------------- kernel 5: final scalar reduction ----------------
__global__ void final_kernel(float* __restrict__ out) {
    __shared__ double s_n[32], s_s[32];
    int tid = threadIdx.x;
    int nv = g_nvalid;
    double nll = 0.0, slp = 0.0;
    for (int m = tid; m < nv; m += blockDim.x) {
        float lse = logf(g_sumexp[m]);
        nll += (double)lse - (double)g_tlogit[m];
        slp += (double)g_sumlogit[m] - (double)V_DIM * (double)lse;
    }
    #pragma unroll
    for (int o = 16; o; o >>= 1) {
        nll += __shfl_down_sync(0xffffffffu, nll, o);
        slp += __shfl_down_sync(0xffffffffu, slp, o);
    }
    if ((tid & 31) == 0) { s_n[tid >> 5] = nll; s_s[tid >> 5] = slp; }
    __syncthreads();
    if (tid < 32) {
        int nw = blockDim.x >> 5;
        nll = (tid < nw) ? s_n[tid] : 0.0;
        slp = (tid < nw) ? s_s[tid] : 0.0;
        #pragma unroll
        for (int o = 16; o; o >>= 1) {
            nll += __shfl_down_sync(0xffffffffu, nll, o);
            slp += __shfl_down_sync(0xffffffffu, slp, o);
        }
        if (tid == 0) {
            double n = (double)nv;
            double loss = 0.9 * (nll / n) - 0.1 * (slp / (n * (double)V_DIM));
            out[0] = (float)loss;
        }
    }
}

// ---------------- launch ----------------
extern "C" void kernel_launch(void* const* d_in, const int* in_sizes, int n_in,
                              void* d_out, int out_size) {
    const int*           targets = (const int*)d_in[0];
    const unsigned char* masks   = (const unsigned char*)d_in[1];
    const float*         outputs = (const float*)d_in[2];
    const float*         W       = (const float*)d_in[3];
    int n_tokens = in_sizes[0];   // 4096

    static int s_attr_done = 0;
    if (!s_attr_done) {
        cudaFuncSetAttribute(gemm_epilogue_kernel,
                             cudaFuncAttributeMaxDynamicSharedMemorySize, SMEM_TOTAL);
        s_attr_done = 1;
    }

    gather_kernel<<<1, 1024>>>(targets, masks, n_tokens);
    build_a_kernel<<<n_tokens, 256>>>(outputs);
    tlogit_kernel<<<n_tokens, 128>>>(outputs, W);

    long ntot = (long)V_PAD * D_DIM;
    int conv_blocks = (int)((ntot / 4 + 255) / 256);
    conv_w_kernel<<<conv_blocks, 256>>>(W);

    dim3 grid((TOKENS_MAX + BM - 1) / BM, N_TILES);
    gemm_epilogue_kernel<<<grid, 256, SMEM_TOTAL>>>();

    final_kernel<<<1, 1024>>>((float*)d_out);
}

// round 15
// speedup vs baseline: 1.0794x; 1.0123x over previous
#include <cuda_runtime.h>
#include <cuda_bf16.h>
#include <cuda_fp16.h>
#include <math.h>
#include <stdint.h>

#define TOKENS_MAX 4096
#define D_DIM 1024
#define V_DIM 50257
#define BM 128
#define BN 256
#define BKB 64                        // K elems (e4m3 bytes) per stage
#define N_TILES 197                   // ceil(50257/256)
#define V_PAD (N_TILES * BN)          // 50432
#define KSTEPS (D_DIM / BKB)          // 16
#define STAGES 3
#define ROW_B 80                      // padded stage row bytes (64 data + 16)
#define A_STAGE (BM * ROW_B)          // 10240
#define B_STAGE (BN * ROW_B)          // 20480
#define STAGE_BYTES (A_STAGE + B_STAGE) // 30720
#define SMEM_TOTAL (STAGES * STAGE_BYTES) // 92160 -> 2 CTAs/SM

#define QA_SCALE 16.0f
#define QW_SCALE 64.0f
#define DEQ (1.0f / (QA_SCALE * QW_SCALE))     // 1/1024
#define DEQ_L2E (DEQ * 1.4426950408889634f)

// ---------------- device-global scratch ----------------
__device__ __align__(128) int8_t g_Wq[(size_t)V_PAD * D_DIM];
__device__ __align__(128) int8_t g_Aq[(size_t)TOKENS_MAX * D_DIM];
__device__ int   g_valid_idx[TOKENS_MAX];
__device__ int   g_tgt[TOKENS_MAX];
__device__ int   g_nvalid;
__device__ float g_sumexp[TOKENS_MAX];
__device__ float g_sumlogit[TOKENS_MAX];
__device__ float g_tlogit[TOKENS_MAX];

__device__ __forceinline__ uint32_t smem_u32(const void* p) {
    uint32_t a;
    asm("{ .reg .u64 t; cvta.to.shared.u64 t, %1; cvt.u32.u64 %0, t; }" : "=r"(a) : "l"(p));
    return a;
}
__device__ __forceinline__ void cp16(uint32_t dst, const void* src) {
    asm volatile("cp.async.cg.shared.global [%0], [%1], 16;\n" :: "r"(dst), "l"(src));
}
__device__ __forceinline__ float ex2f(float x) {
    float r;
    asm("ex2.approx.f32 %0, %1;" : "=f"(r) : "f"(x));
    return r;
}
__device__ __forceinline__ __half2 h2ex2(__half2 x) {
    uint32_t r, xi = *(const uint32_t*)&x;
    asm("ex2.approx.f16x2 %0, %1;" : "=r"(r) : "r"(xi));
    return *(__half2*)&r;
}
__device__ __forceinline__ uint16_t f2e4m3x2(float hi, float lo) {
    uint16_t r;
    asm("cvt.rn.satfinite.e4m3x2.f32 %0, %1, %2;" : "=h"(r) : "f"(hi), "f"(lo));
    return r;
}
__device__ __forceinline__ uint32_t pack4_e4m3(float x0, float x1, float x2, float x3) {
    uint32_t lo = f2e4m3x2(x1, x0);
    uint32_t hi = f2e4m3x2(x3, x2);
    return lo | (hi << 16);
}
#define LDSM_X4(R0, R1, R2, R3, addr)                                          \
    asm volatile("ldmatrix.sync.aligned.m8n8.x4.shared.b16 {%0,%1,%2,%3}, [%4];" \
                 : "=r"(R0), "=r"(R1), "=r"(R2), "=r"(R3) : "r"(addr))
// fp8 MMA with f16 accumulators (2 regs)
#define MMA_FP8H(d, a, b0, b1)                                                 \
    asm volatile("mma.sync.aligned.m16n8k32.row.col.f16.e4m3.e4m3.f16 "        \
                 "{%0,%1}, {%2,%3,%4,%5}, {%6,%7}, {%0,%1};"                   \
                 : "+r"((d)[0]), "+r"((d)[1])                                  \
                 : "r"((a)[0]), "r"((a)[1]), "r"((a)[2]), "r"((a)[3]),         \
                   "r"(b0), "r"(b1))

// ---------------- kernel 1: mask-dtype detect + compact valid tokens ----------------
__global__ void gather_kernel(const int* __restrict__ targets,
                              const unsigned char* __restrict__ masks_raw,
                              int n_tokens) {
    __shared__ int s_isu8;
    __shared__ int wsum[32];
    int tid = threadIdx.x;
    if (tid == 0) s_isu8 = 0;
    __syncthreads();

    int flag = 0;
    for (int i = tid; i < n_tokens; i += blockDim.x)
        if ((i & 3) != 0 && masks_raw[i] != 0) flag = 1;
    if (flag) atomicOr(&s_isu8, 1);
    __syncthreads();
    const bool isu8 = (s_isu8 != 0);
    const int* masks_i32 = (const int*)masks_raw;

    int C = (n_tokens + blockDim.x - 1) / blockDim.x;
    int start = tid * C;
    int end = min(start + C, n_tokens);
    int cnt = 0;
    for (int i = start; i < end; i++)
        cnt += isu8 ? (masks_raw[i] != 0) : (masks_i32[i] != 0);

    int lane = tid & 31, wid = tid >> 5;
    int v = cnt;
    #pragma unroll
    for (int o = 1; o < 32; o <<= 1) {
        int t = __shfl_up_sync(0xffffffffu, v, o);
        if (lane >= o) v += t;
    }
    if (lane == 31) wsum[wid] = v;
    __syncthreads();
    if (wid == 0) {
        int nw = blockDim.x >> 5;
        int w = (lane < nw) ? wsum[lane] : 0;
        #pragma unroll
        for (int o = 1; o < 32; o <<= 1) {
            int t = __shfl_up_sync(0xffffffffu, w, o);
            if (lane >= o) w += t;
        }
        wsum[lane] = w;
    }
    __syncthreads();
    int excl = v - cnt + (wid > 0 ? wsum[wid - 1] : 0);

    int off = excl;
    for (int i = start; i < end; i++) {
        bool mk = isu8 ? (masks_raw[i] != 0) : (masks_i32[i] != 0);
        if (mk) {
            g_valid_idx[off] = i;
            g_tgt[off] = targets[i];
            off++;
        }
    }
    if (tid == blockDim.x - 1) g_nvalid = excl + cnt;
}

// ---------------- kernel 2: gather + quantize A + exact target logit (fused) ----------------
__global__ void build_a_kernel(const float* __restrict__ outputs,
                               const float* __restrict__ W) {
    __shared__ float ws[8];
    int m = blockIdx.x;
    int tid = threadIdx.x;              // 256 threads
    int lane = tid & 31, wid = tid >> 5;
    if (tid == 0) {
        g_sumexp[m] = 0.f;
        g_sumlogit[m] = 0.f;
    }
    int nv = g_nvalid;
    uint32_t* dst = (uint32_t*)(g_Aq + (size_t)m * D_DIM);
    if (m < nv) {
        const float* arow = outputs + (size_t)g_valid_idx[m] * D_DIM;
        const float* wrow = W + (size_t)g_tgt[m] * D_DIM;
        // 256 threads x 4 elems = 1024: quantize + dot in one pass
        float4 a = *(const float4*)(arow + tid * 4);
        float4 w = *(const float4*)(wrow + tid * 4);
        dst[tid] = pack4_e4m3(a.x * QA_SCALE, a.y * QA_SCALE,
                              a.z * QA_SCALE, a.w * QA_SCALE);
        float s = a.x * w.x + a.y * w.y + a.z * w.z + a.w * w.w;
        #pragma unroll
        for (int o = 16; o; o >>= 1) s += __shfl_down_sync(0xffffffffu, s, o);
        if (lane == 0) ws[wid] = s;
        __syncthreads();
        if (wid == 0) {
            float t = (lane < 8) ? ws[lane] : 0.f;
            #pragma unroll
            for (int o = 4; o; o >>= 1) t += __shfl_down_sync(0xffffffffu, t, o);
            if (lane == 0) g_tlogit[m] = t;
        }
    } else {
        dst[tid] = 0u;
    }
}

// ---------------- kernel 3: W fp32 -> e4m3, 16 elems/thread (zero-pad to V_PAD) ----------------
__global__ void conv_w_kernel(const float* __restrict__ W) {
    long i = ((long)blockIdx.x * blockDim.x + threadIdx.x) * 16;
    const long nreal = (long)V_DIM * D_DIM;
    const long ntot  = (long)V_PAD * D_DIM;
    if (i >= ntot) return;
    uint4 out = make_uint4(0u, 0u, 0u, 0u);
    if (i + 16 <= nreal) {
        float4 v0 = *(const float4*)(W + i);
        float4 v1 = *(const float4*)(W + i + 4);
        float4 v2 = *(const float4*)(W + i + 8);
        float4 v3 = *(const float4*)(W + i + 12);
        out.x = pack4_e4m3(v0.x * QW_SCALE, v0.y * QW_SCALE, v0.z * QW_SCALE, v0.w * QW_SCALE);
        out.y = pack4_e4m3(v1.x * QW_SCALE, v1.y * QW_SCALE, v1.z * QW_SCALE, v1.w * QW_SCALE);
        out.z = pack4_e4m3(v2.x * QW_SCALE, v2.y * QW_SCALE, v2.z * QW_SCALE, v2.w * QW_SCALE);
        out.w = pack4_e4m3(v3.x * QW_SCALE, v3.y * QW_SCALE, v3.z * QW_SCALE, v3.w * QW_SCALE);
    } else if (i < nreal) {
        // partial tail (V_DIM*D_DIM is a multiple of 16 actually; defensive)
        uint32_t tmp[4] = {0u, 0u, 0u, 0u};
        for (int e = 0; e < 16 && i + e < nreal; e++) {
            float v = W[i + e] * QW_SCALE;
            uint16_t h = f2e4m3x2(0.f, v);
            ((uint8_t*)tmp)[e] = (uint8_t)(h & 0xff);
        }
        out = *(uint4*)tmp;
    }
    *(uint4*)(g_Wq + i) = out;
}

// ---------------- epilogue helper (half2 fast path, no target logic) ----------------
template <bool CHK>
__device__ __forceinline__ void epilogue(uint32_t (&acc)[4][8][2], int m0w, int n0w,
                                         int nv, int lane) {
    const __half2 dq = __float2half2_rn(DEQ_L2E);
    #pragma unroll
    for (int i = 0; i < 4; i++) {
        int r0 = m0w + i * 16 + (lane >> 2);
        int r1 = r0 + 8;
        float se0, sr0, se1, sr1;
        if (!CHK) {
            __half2 hse0 = __float2half2_rn(0.f);
            __half2 hsr0 = hse0, hse1 = hse0, hsr1 = hse0;
            #pragma unroll
            for (int g = 0; g < 8; g++) {
                __half2 a0 = *(const __half2*)&acc[i][g][0];
                __half2 a1 = *(const __half2*)&acc[i][g][1];
                hse0 = __hadd2(hse0, h2ex2(__hmul2(a0, dq)));
                hsr0 = __hadd2(hsr0, a0);
                hse1 = __hadd2(hse1, h2ex2(__hmul2(a1, dq)));
                hsr1 = __hadd2(hsr1, a1);
            }
            float2 f;
            f = __half22float2(hse0); se0 = f.x + f.y;
            f = __half22float2(hsr0); sr0 = f.x + f.y;
            f = __half22float2(hse1); se1 = f.x + f.y;
            f = __half22float2(hsr1); sr1 = f.x + f.y;
        } else {
            se0 = sr0 = se1 = sr1 = 0.f;
            #pragma unroll
            for (int g = 0; g < 8; g++) {
                int c0 = n0w + g * 8 + (lane & 3) * 2;
                float2 p0 = __half22float2(*(const __half2*)&acc[i][g][0]);
                float2 p1 = __half22float2(*(const __half2*)&acc[i][g][1]);
                if (c0 < V_DIM) {
                    se0 += ex2f(p0.x * DEQ_L2E); sr0 += p0.x;
                    se1 += ex2f(p1.x * DEQ_L2E); sr1 += p1.x;
                }
                if (c0 + 1 < V_DIM) {
                    se0 += ex2f(p0.y * DEQ_L2E); sr0 += p0.y;
                    se1 += ex2f(p1.y * DEQ_L2E); sr1 += p1.y;
                }
            }
        }
        #pragma unroll
        for (int o = 1; o <= 2; o <<= 1) {
            se0 += __shfl_xor_sync(0xffffffffu, se0, o);
            sr0 += __shfl_xor_sync(0xffffffffu, sr0, o);
            se1 += __shfl_xor_sync(0xffffffffu, se1, o);
            sr1 += __shfl_xor_sync(0xffffffffu, sr1, o);
        }
        if ((lane & 3) == 0) {
            if (r0 < nv) {
                atomicAdd(&g_sumexp[r0], se0);
                atomicAdd(&g_sumlogit[r0], sr0 * DEQ);
            }
            if (r1 < nv) {
                atomicAdd(&g_sumexp[r1], se1);
                atomicAdd(&g_sumlogit[r1], sr1 * DEQ);
            }
        }
    }
}

// ---------------- kernel 4: 128x256 FP8 QMMA (f16 acc), warp tile 64x64, 2 CTAs/SM ----------------
__global__ void __launch_bounds__(256, 2) gemm_epilogue_kernel() {
    extern __shared__ char smem[];
    uint32_t sb = smem_u32(smem);

    int nv = g_nvalid;
    int m0 = blockIdx.x * BM;
    if (m0 >= nv) return;
    int n0 = blockIdx.y * BN;

    int tid = threadIdx.x;
    int warp = tid >> 5, lane = tid & 31;
    int wm = warp & 1;        // A rows wm*64..+63
    int wn = warp >> 1;       // B rows wn*64..+63 (4 n-slices of 64)

    // cp.async slots per stage: A 2 chunks, B 4 chunks per thread (16B each)
    uint32_t adst[2], aofs[2], bdst[4], bofs[4];
    const char* Ag = (const char*)g_Aq;
    const char* Wg = (const char*)g_Wq;
    #pragma unroll
    for (int i = 0; i < 2; i++) {
        int c = tid + i * 256;             // 512 chunks = 128 rows x 4
        int r = c >> 2, cc = (c & 3) << 4;
        adst[i] = (uint32_t)(r * ROW_B + cc);
        aofs[i] = (uint32_t)((m0 + r) * D_DIM + cc);
    }
    #pragma unroll
    for (int i = 0; i < 4; i++) {
        int c = tid + i * 256;             // 1024 chunks = 256 rows x 4
        int r = c >> 2, cc = (c & 3) << 4;
        bdst[i] = (uint32_t)(r * ROW_B + cc);
        bofs[i] = (uint32_t)((n0 + r) * D_DIM + cc);
    }

    // ldmatrix base offsets (fragment layout validated R8-R14)
    uint32_t aoff = sb +
        (uint32_t)(((lane & 7) + ((lane >> 3) & 1) * 8 + wm * 64) * ROW_B + (lane >> 4) * 16);
    uint32_t boff = sb + A_STAGE +
        (uint32_t)(((lane & 7) + (lane >> 4) * 8 + wn * 64) * ROW_B + ((lane >> 3) & 1) * 16);

    uint32_t acc[4][8][2];
    #pragma unroll
    for (int i = 0; i < 4; i++)
        #pragma unroll
        for (int g = 0; g < 8; g++) {
            acc[i][g][0] = 0u;
            acc[i][g][1] = 0u;
        }

    // prologue: 2 stages in flight
    #pragma unroll
    for (int s = 0; s < 2; s++) {
        uint32_t ab = sb + s * STAGE_BYTES;
        uint32_t kb = (uint32_t)s * BKB;
        #pragma unroll
        for (int i = 0; i < 2; i++) cp16(ab + adst[i], Ag + aofs[i] + kb);
        #pragma unroll
        for (int i = 0; i < 4; i++) cp16(ab + A_STAGE + bdst[i], Wg + bofs[i] + kb);
        asm volatile("cp.async.commit_group;" ::: "memory");
    }

    for (int j = 0; j < KSTEPS; j++) {
        asm volatile("cp.async.wait_group 1;" ::: "memory");
        __syncthreads();   // one barrier per K-step (16 total)

        if (j + 2 < KSTEPS) {
            int s = (j + 2) % STAGES;
            uint32_t ab = sb + s * STAGE_BYTES;
            uint32_t kb = (uint32_t)(j + 2) * BKB;
            #pragma unroll
            for (int i = 0; i < 2; i++) cp16(ab + adst[i], Ag + aofs[i] + kb);
            #pragma unroll
            for (int i = 0; i < 4; i++) cp16(ab + A_STAGE + bdst[i], Wg + bofs[i] + kb);
        }
        asm volatile("cp.async.commit_group;" ::: "memory");

        uint32_t sbase = (uint32_t)((j % STAGES) * STAGE_BYTES);
        #pragma unroll
        for (int kk = 0; kk < 2; kk++) {        // 2 x k=32 sub-steps
            uint32_t af[4][4], bf[4][4];
            #pragma unroll
            for (int i = 0; i < 4; i++)
                LDSM_X4(af[i][0], af[i][1], af[i][2], af[i][3],
                        aoff + sbase + (uint32_t)(i * 16 * ROW_B + kk * 32));
            #pragma unroll
            for (int p = 0; p < 4; p++)
                LDSM_X4(bf[p][0], bf[p][1], bf[p][2], bf[p][3],
                        boff + sbase + (uint32_t)(p * 16 * ROW_B + kk * 32));
            #pragma unroll
            for (int i = 0; i < 4; i++)
                #pragma unroll
                for (int p = 0; p < 4; p++) {
                    MMA_FP8H(acc[i][2 * p],     af[i], bf[p][0], bf[p][1]);
                    MMA_FP8H(acc[i][2 * p + 1], af[i], bf[p][2], bf[p][3]);
                }
        }
    }

    // ---- register-direct epilogue ----
    int m0w = m0 + wm * 64;
    int n0w = n0 + wn * 64;
    if (n0 + BN <= V_DIM) epilogue<false>(acc, m0w, n0w, nv, lane);
    else                  epilogue<true >(acc, m0w, n0w, nv, lane);
}

// ---------------- kernel 5: final scalar reduction ----------------
__global__ void final_kernel(float* __restrict__ out) {
    __shared__ double s_n[32], s_s[32];
    int tid = threadIdx.x;
    int nv = g_nvalid;
    double nll = 0.0, slp = 0.0;
    for (int m = tid; m < nv; m += blockDim.x) {
        float lse = logf(g_sumexp[m]);
        nll += (double)lse - (double)g_tlogit[m];
        slp += (double)g_sumlogit[m] - (double)V_DIM * (double)lse;
    }
    #pragma unroll
    for (int o = 16; o; o >>= 1) {
        nll += __shfl_down_sync(0xffffffffu, nll, o);
        slp += __shfl_down_sync(0xffffffffu, slp, o);
    }
    if ((tid & 31) == 0) { s_n[tid >> 5] = nll; s_s[tid >> 5] = slp; }
    __syncthreads();
    if (tid < 32) {
        int nw = blockDim.x >> 5;
        nll = (tid < nw) ? s_n[tid] : 0.0;
        slp = (tid < nw) ? s_s[tid] : 0.0;
        #pragma unroll
        for (int o = 16; o; o >>= 1) {
            nll += __shfl_down_sync(0xffffffffu, nll, o);
            slp += __shfl_down_sync(0xffffffffu, slp, o);
        }
        if (tid == 0) {
            double n = (double)nv;
            double loss = 0.9 * (nll / n) - 0.1 * (slp / (n * (double)V_DIM));
            out[0] = (float)loss;
        }
    }
}

// ---------------- launch ----------------
extern "C" void kernel_launch(void* const* d_in, const int* in_sizes, int n_in,
                              void* d_out, int out_size) {
    const int*           targets = (const int*)d_in[0];
    const unsigned char* masks   = (const unsigned char*)d_in[1];
    const float*         outputs = (const float*)d_in[2];
    const float*         W       = (const float*)d_in[3];
    int n_tokens = in_sizes[0];   // 4096

    static int s_attr_done = 0;
    if (!s_attr_done) {
        cudaFuncSetAttribute(gemm_epilogue_kernel,
                             cudaFuncAttributeMaxDynamicSharedMemorySize, SMEM_TOTAL);
        s_attr_done = 1;
    }

    gather_kernel<<<1, 1024>>>(targets, masks, n_tokens);
    build_a_kernel<<<n_tokens, 256>>>(outputs, W);

    long ntot = (long)V_PAD * D_DIM;
    int conv_blocks = (int)((ntot / 16 + 255) / 256);
    conv_w_kernel<<<conv_blocks, 256>>>(W);

    dim3 grid((TOKENS_MAX + BM - 1) / BM, N_TILES);
    gemm_epilogue_kernel<<<grid, 256, SMEM_TOTAL>>>();

    final_kernel<<<1, 1024>>>((float*)d_out);
}

// round 16
// speedup vs baseline: 1.1343x; 1.0509x over previous
#include <cuda_runtime.h>
#include <cuda_bf16.h>
#include <cuda_fp16.h>
#include <math.h>
#include <stdint.h>

#define TOKENS_MAX 4096
#define D_DIM 1024
#define V_DIM 50257
#define BM 128
#define BN 256
#define BKB 128                       // K elems (e4m3 bytes) per stage
#define N_TILES 197                   // ceil(50257/256)
#define V_PAD (N_TILES * BN)          // 50432
#define KSTEPS (D_DIM / BKB)          // 8
#define STAGES 2
#define ROW_B 144                     // padded stage row bytes (128 data + 16)
#define A_STAGE (BM * ROW_B)          // 18432
#define B_STAGE (BN * ROW_B)          // 36864
#define STAGE_BYTES (A_STAGE + B_STAGE) // 55296
#define SMEM_TOTAL (STAGES * STAGE_BYTES) // 110592 -> 2 CTAs/SM

#define QA_SCALE 16.0f
#define QW_SCALE 64.0f
#define DEQ (1.0f / (QA_SCALE * QW_SCALE))     // 1/1024
#define DEQ_L2E (DEQ * 1.4426950408889634f)

// ---------------- device-global scratch ----------------
__device__ __align__(128) int8_t g_Wq[(size_t)V_PAD * D_DIM];
__device__ __align__(128) int8_t g_Aq[(size_t)TOKENS_MAX * D_DIM];
__device__ int   g_valid_idx[TOKENS_MAX];
__device__ int   g_tgt[TOKENS_MAX];
__device__ int   g_nvalid;
__device__ float g_sumexp[TOKENS_MAX];
__device__ float g_sumlogit[TOKENS_MAX];
__device__ float g_tlogit[TOKENS_MAX];

__device__ __forceinline__ uint32_t smem_u32(const void* p) {
    uint32_t a;
    asm("{ .reg .u64 t; cvta.to.shared.u64 t, %1; cvt.u32.u64 %0, t; }" : "=r"(a) : "l"(p));
    return a;
}
__device__ __forceinline__ void cp16(uint32_t dst, const void* src) {
    asm volatile("cp.async.cg.shared.global [%0], [%1], 16;\n" :: "r"(dst), "l"(src));
}
__device__ __forceinline__ float ex2f(float x) {
    float r;
    asm("ex2.approx.f32 %0, %1;" : "=f"(r) : "f"(x));
    return r;
}
__device__ __forceinline__ __half2 h2ex2(__half2 x) {
    uint32_t r, xi = *(const uint32_t*)&x;
    asm("ex2.approx.f16x2 %0, %1;" : "=r"(r) : "r"(xi));
    return *(__half2*)&r;
}
__device__ __forceinline__ uint16_t f2e4m3x2(float hi, float lo) {
    uint16_t r;
    asm("cvt.rn.satfinite.e4m3x2.f32 %0, %1, %2;" : "=h"(r) : "f"(hi), "f"(lo));
    return r;
}
__device__ __forceinline__ uint32_t pack4_e4m3(float x0, float x1, float x2, float x3) {
    uint32_t lo = f2e4m3x2(x1, x0);
    uint32_t hi = f2e4m3x2(x3, x2);
    return lo | (hi << 16);
}
#define LDSM_X4(R0, R1, R2, R3, addr)                                          \
    asm volatile("ldmatrix.sync.aligned.m8n8.x4.shared.b16 {%0,%1,%2,%3}, [%4];" \
                 : "=r"(R0), "=r"(R1), "=r"(R2), "=r"(R3) : "r"(addr))
// fp8 MMA with f16 accumulators (2 regs)
#define MMA_FP8H(d, a, b0, b1)                                                 \
    asm volatile("mma.sync.aligned.m16n8k32.row.col.f16.e4m3.e4m3.f16 "        \
                 "{%0,%1}, {%2,%3,%4,%5}, {%6,%7}, {%0,%1};"                   \
                 : "+r"((d)[0]), "+r"((d)[1])                                  \
                 : "r"((a)[0]), "r"((a)[1]), "r"((a)[2]), "r"((a)[3]),         \
                   "r"(b0), "r"(b1))

// ---------------- kernel 1: mask-dtype detect + compact valid tokens ----------------
__global__ void gather_kernel(const int* __restrict__ targets,
                              const unsigned char* __restrict__ masks_raw,
                              int n_tokens) {
    __shared__ int s_isu8;
    __shared__ int wsum[32];
    int tid = threadIdx.x;
    if (tid == 0) s_isu8 = 0;
    __syncthreads();

    int flag = 0;
    for (int i = tid; i < n_tokens; i += blockDim.x)
        if ((i & 3) != 0 && masks_raw[i] != 0) flag = 1;
    if (flag) atomicOr(&s_isu8, 1);
    __syncthreads();
    const bool isu8 = (s_isu8 != 0);
    const int* masks_i32 = (const int*)masks_raw;

    int C = (n_tokens + blockDim.x - 1) / blockDim.x;
    int start = tid * C;
    int end = min(start + C, n_tokens);
    int cnt = 0;
    for (int i = start; i < end; i++)
        cnt += isu8 ? (masks_raw[i] != 0) : (masks_i32[i] != 0);

    int lane = tid & 31, wid = tid >> 5;
    int v = cnt;
    #pragma unroll
    for (int o = 1; o < 32; o <<= 1) {
        int t = __shfl_up_sync(0xffffffffu, v, o);
        if (lane >= o) v += t;
    }
    if (lane == 31) wsum[wid] = v;
    __syncthreads();
    if (wid == 0) {
        int nw = blockDim.x >> 5;
        int w = (lane < nw) ? wsum[lane] : 0;
        #pragma unroll
        for (int o = 1; o < 32; o <<= 1) {
            int t = __shfl_up_sync(0xffffffffu, w, o);
            if (lane >= o) w += t;
        }
        wsum[lane] = w;
    }
    __syncthreads();
    int excl = v - cnt + (wid > 0 ? wsum[wid - 1] : 0);

    int off = excl;
    for (int i = start; i < end; i++) {
        bool mk = isu8 ? (masks_raw[i] != 0) : (masks_i32[i] != 0);
        if (mk) {
            g_valid_idx[off] = i;
            g_tgt[off] = targets[i];
            off++;
        }
    }
    if (tid == blockDim.x - 1) g_nvalid = excl + cnt;
}

// ---------------- kernel 2: gather + quantize A + exact target logit (fused) ----------------
__global__ void build_a_kernel(const float* __restrict__ outputs,
                               const float* __restrict__ W) {
    __shared__ float ws[8];
    int m = blockIdx.x;
    int tid = threadIdx.x;              // 256 threads
    int lane = tid & 31, wid = tid >> 5;
    if (tid == 0) {
        g_sumexp[m] = 0.f;
        g_sumlogit[m] = 0.f;
    }
    int nv = g_nvalid;
    uint32_t* dst = (uint32_t*)(g_Aq + (size_t)m * D_DIM);
    if (m < nv) {
        const float* arow = outputs + (size_t)g_valid_idx[m] * D_DIM;
        const float* wrow = W + (size_t)g_tgt[m] * D_DIM;
        float4 a = *(const float4*)(arow + tid * 4);
        float4 w = *(const float4*)(wrow + tid * 4);
        dst[tid] = pack4_e4m3(a.x * QA_SCALE, a.y * QA_SCALE,
                              a.z * QA_SCALE, a.w * QA_SCALE);
        float s = a.x * w.x + a.y * w.y + a.z * w.z + a.w * w.w;
        #pragma unroll
        for (int o = 16; o; o >>= 1) s += __shfl_down_sync(0xffffffffu, s, o);
        if (lane == 0) ws[wid] = s;
        __syncthreads();
        if (wid == 0) {
            float t = (lane < 8) ? ws[lane] : 0.f;
            #pragma unroll
            for (int o = 4; o; o >>= 1) t += __shfl_down_sync(0xffffffffu, t, o);
            if (lane == 0) g_tlogit[m] = t;
        }
    } else {
        dst[tid] = 0u;
    }
}

// ---------------- kernel 3: W fp32 -> e4m3, 16 elems/thread (zero-pad to V_PAD) ----------------
__global__ void conv_w_kernel(const float* __restrict__ W) {
    long i = ((long)blockIdx.x * blockDim.x + threadIdx.x) * 16;
    const long nreal = (long)V_DIM * D_DIM;
    const long ntot  = (long)V_PAD * D_DIM;
    if (i >= ntot) return;
    uint4 out = make_uint4(0u, 0u, 0u, 0u);
    if (i + 16 <= nreal) {
        float4 v0 = *(const float4*)(W + i);
        float4 v1 = *(const float4*)(W + i + 4);
        float4 v2 = *(const float4*)(W + i + 8);
        float4 v3 = *(const float4*)(W + i + 12);
        out.x = pack4_e4m3(v0.x * QW_SCALE, v0.y * QW_SCALE, v0.z * QW_SCALE, v0.w * QW_SCALE);
        out.y = pack4_e4m3(v1.x * QW_SCALE, v1.y * QW_SCALE, v1.z * QW_SCALE, v1.w * QW_SCALE);
        out.z = pack4_e4m3(v2.x * QW_SCALE, v2.y * QW_SCALE, v2.z * QW_SCALE, v2.w * QW_SCALE);
        out.w = pack4_e4m3(v3.x * QW_SCALE, v3.y * QW_SCALE, v3.z * QW_SCALE, v3.w * QW_SCALE);
    } else if (i < nreal) {
        uint32_t tmp[4] = {0u, 0u, 0u, 0u};
        for (int e = 0; e < 16 && i + e < nreal; e++) {
            float v = W[i + e] * QW_SCALE;
            uint16_t h = f2e4m3x2(0.f, v);
            ((uint8_t*)tmp)[e] = (uint8_t)(h & 0xff);
        }
        out = *(uint4*)tmp;
    }
    *(uint4*)(g_Wq + i) = out;
}

// ---------------- epilogue helper (half2 fast path, no target logic) ----------------
template <bool CHK>
__device__ __forceinline__ void epilogue(uint32_t (&acc)[4][8][2], int m0w, int n0w,
                                         int nv, int lane) {
    const __half2 dq = __float2half2_rn(DEQ_L2E);
    #pragma unroll
    for (int i = 0; i < 4; i++) {
        int r0 = m0w + i * 16 + (lane >> 2);
        int r1 = r0 + 8;
        float se0, sr0, se1, sr1;
        if (!CHK) {
            __half2 hse0 = __float2half2_rn(0.f);
            __half2 hsr0 = hse0, hse1 = hse0, hsr1 = hse0;
            #pragma unroll
            for (int g = 0; g < 8; g++) {
                __half2 a0 = *(const __half2*)&acc[i][g][0];
                __half2 a1 = *(const __half2*)&acc[i][g][1];
                hse0 = __hadd2(hse0, h2ex2(__hmul2(a0, dq)));
                hsr0 = __hadd2(hsr0, a0);
                hse1 = __hadd2(hse1, h2ex2(__hmul2(a1, dq)));
                hsr1 = __hadd2(hsr1, a1);
            }
            float2 f;
            f = __half22float2(hse0); se0 = f.x + f.y;
            f = __half22float2(hsr0); sr0 = f.x + f.y;
            f = __half22float2(hse1); se1 = f.x + f.y;
            f = __half22float2(hsr1); sr1 = f.x + f.y;
        } else {
            se0 = sr0 = se1 = sr1 = 0.f;
            #pragma unroll
            for (int g = 0; g < 8; g++) {
                int c0 = n0w + g * 8 + (lane & 3) * 2;
                float2 p0 = __half22float2(*(const __half2*)&acc[i][g][0]);
                float2 p1 = __half22float2(*(const __half2*)&acc[i][g][1]);
                if (c0 < V_DIM) {
                    se0 += ex2f(p0.x * DEQ_L2E); sr0 += p0.x;
                    se1 += ex2f(p1.x * DEQ_L2E); sr1 += p1.x;
                }
                if (c0 + 1 < V_DIM) {
                    se0 += ex2f(p0.y * DEQ_L2E); sr0 += p0.y;
                    se1 += ex2f(p1.y * DEQ_L2E); sr1 += p1.y;
                }
            }
        }
        #pragma unroll
        for (int o = 1; o <= 2; o <<= 1) {
            se0 += __shfl_xor_sync(0xffffffffu, se0, o);
            sr0 += __shfl_xor_sync(0xffffffffu, sr0, o);
            se1 += __shfl_xor_sync(0xffffffffu, se1, o);
            sr1 += __shfl_xor_sync(0xffffffffu, sr1, o);
        }
        if ((lane & 3) == 0) {
            if (r0 < nv) {
                atomicAdd(&g_sumexp[r0], se0);
                atomicAdd(&g_sumlogit[r0], sr0 * DEQ);
            }
            if (r1 < nv) {
                atomicAdd(&g_sumexp[r1], se1);
                atomicAdd(&g_sumlogit[r1], sr1 * DEQ);
            }
        }
    }
}

// ---------------- kernel 4: 128x256x(K=128B) FP8 QMMA (f16 acc), 2-stage ring, 2 CTAs/SM ----------------
__global__ void __launch_bounds__(256, 2) gemm_epilogue_kernel() {
    extern __shared__ char smem[];
    uint32_t sb = smem_u32(smem);

    int nv = g_nvalid;
    int m0 = blockIdx.x * BM;
    if (m0 >= nv) return;
    int n0 = blockIdx.y * BN;

    int tid = threadIdx.x;
    int warp = tid >> 5, lane = tid & 31;
    int wm = warp & 1;        // A rows wm*64..+63
    int wn = warp >> 1;       // B rows wn*64..+63 (4 n-slices of 64)

    // cp.async slots per stage: A 4 chunks, B 8 chunks per thread (16B each)
    uint32_t adst[4], aofs[4], bdst[8], bofs[8];
    const char* Ag = (const char*)g_Aq;
    const char* Wg = (const char*)g_Wq;
    #pragma unroll
    for (int i = 0; i < 4; i++) {
        int c = tid + i * 256;             // 1024 chunks = 128 rows x 8
        int r = c >> 3, cc = (c & 7) << 4;
        adst[i] = (uint32_t)(r * ROW_B + cc);
        aofs[i] = (uint32_t)((m0 + r) * D_DIM + cc);
    }
    #pragma unroll
    for (int i = 0; i < 8; i++) {
        int c = tid + i * 256;             // 2048 chunks = 256 rows x 8
        int r = c >> 3, cc = (c & 7) << 4;
        bdst[i] = (uint32_t)(r * ROW_B + cc);
        bofs[i] = (uint32_t)((n0 + r) * D_DIM + cc);
    }

    // ldmatrix base offsets (fragment layout validated R8-R15; ROW_B=144 validated R8-R12)
    uint32_t aoff = sb +
        (uint32_t)(((lane & 7) + ((lane >> 3) & 1) * 8 + wm * 64) * ROW_B + (lane >> 4) * 16);
    uint32_t boff = sb + A_STAGE +
        (uint32_t)(((lane & 7) + (lane >> 4) * 8 + wn * 64) * ROW_B + ((lane >> 3) & 1) * 16);

    uint32_t acc[4][8][2];
    #pragma unroll
    for (int i = 0; i < 4; i++)
        #pragma unroll
        for (int g = 0; g < 8; g++) {
            acc[i][g][0] = 0u;
            acc[i][g][1] = 0u;
        }

    // prologue: stage 0 only (depth-2, distance-1 pipeline)
    {
        #pragma unroll
        for (int i = 0; i < 4; i++) cp16(sb + adst[i], Ag + aofs[i]);
        #pragma unroll
        for (int i = 0; i < 8; i++) cp16(sb + A_STAGE + bdst[i], Wg + bofs[i]);
        asm volatile("cp.async.commit_group;" ::: "memory");
    }

    for (int j = 0; j < KSTEPS; j++) {
        asm volatile("cp.async.wait_group 0;" ::: "memory");
        __syncthreads();   // one barrier per K-step (8 total)

        // prefetch step j+1 into the other buffer (last read at step j-1, sealed above)
        if (j + 1 < KSTEPS) {
            uint32_t ab = sb + ((j + 1) & 1) * STAGE_BYTES;
            uint32_t kb = (uint32_t)(j + 1) * BKB;
            #pragma unroll
            for (int i = 0; i < 4; i++) cp16(ab + adst[i], Ag + aofs[i] + kb);
            #pragma unroll
            for (int i = 0; i < 8; i++) cp16(ab + A_STAGE + bdst[i], Wg + bofs[i] + kb);
        }
        asm volatile("cp.async.commit_group;" ::: "memory");

        uint32_t sbase = (uint32_t)((j & 1) * STAGE_BYTES);
        #pragma unroll
        for (int kk = 0; kk < 4; kk++) {        // 4 x k=32 sub-steps
            uint32_t af[4][4], bf[4][4];
            #pragma unroll
            for (int i = 0; i < 4; i++)
                LDSM_X4(af[i][0], af[i][1], af[i][2], af[i][3],
                        aoff + sbase + (uint32_t)(i * 16 * ROW_B + kk * 32));
            #pragma unroll
            for (int p = 0; p < 4; p++)
                LDSM_X4(bf[p][0], bf[p][1], bf[p][2], bf[p][3],
                        boff + sbase + (uint32_t)(p * 16 * ROW_B + kk * 32));
            #pragma unroll
            for (int i = 0; i < 4; i++)
                #pragma unroll
                for (int p = 0; p < 4; p++) {
                    MMA_FP8H(acc[i][2 * p],     af[i], bf[p][0], bf[p][1]);
                    MMA_FP8H(acc[i][2 * p + 1], af[i], bf[p][2], bf[p][3]);
                }
        }
    }

    // ---- register-direct epilogue ----
    int m0w = m0 + wm * 64;
    int n0w = n0 + wn * 64;
    if (n0 + BN <= V_DIM) epilogue<false>(acc, m0w, n0w, nv, lane);
    else                  epilogue<true >(acc, m0w, n0w, nv, lane);
}

// ---------------- kernel 5: final scalar reduction ----------------
__global__ void final_kernel(float* __restrict__ out) {
    __shared__ double s_n[32], s_s[32];
    int tid = threadIdx.x;
    int nv = g_nvalid;
    double nll = 0.0, slp = 0.0;
    for (int m = tid; m < nv; m += blockDim.x) {
        float lse = logf(g_sumexp[m]);
        nll += (double)lse - (double)g_tlogit[m];
        slp += (double)g_sumlogit[m] - (double)V_DIM * (double)lse;
    }
    #pragma unroll
    for (int o = 16; o; o >>= 1) {
        nll += __shfl_down_sync(0xffffffffu, nll, o);
        slp += __shfl_down_sync(0xffffffffu, slp, o);
    }
    if ((tid & 31) == 0) { s_n[tid >> 5] = nll; s_s[tid >> 5] = slp; }
    __syncthreads();
    if (tid < 32) {
        int nw = blockDim.x >> 5;
        nll = (tid < nw) ? s_n[tid] : 0.0;
        slp = (tid < nw) ? s_s[tid] : 0.0;
        #pragma unroll
        for (int o = 16; o; o >>= 1) {
            nll += __shfl_down_sync(0xffffffffu, nll, o);
            slp += __shfl_down_sync(0xffffffffu, slp, o);
        }
        if (tid == 0) {
            double n = (double)nv;
            double loss = 0.9 * (nll / n) - 0.1 * (slp / (n * (double)V_DIM));
            out[0] = (float)loss;
        }
    }
}

// ---------------- launch ----------------
extern "C" void kernel_launch(void* const* d_in, const int* in_sizes, int n_in,
                              void* d_out, int out_size) {
    const int*           targets = (const int*)d_in[0];
    const unsigned char* masks   = (const unsigned char*)d_in[1];
    const float*         outputs = (const float*)d_in[2];
    const float*         W       = (const float*)d_in[3];
    int n_tokens = in_sizes[0];   // 4096

    static int s_attr_done = 0;
    if (!s_attr_done) {
        cudaFuncSetAttribute(gemm_epilogue_kernel,
                             cudaFuncAttributeMaxDynamicSharedMemorySize, SMEM_TOTAL);
        s_attr_done = 1;
    }

    gather_kernel<<<1, 1024>>>(targets, masks, n_tokens);
    build_a_kernel<<<n_tokens, 256>>>(outputs, W);

    long ntot = (long)V_PAD * D_DIM;
    int conv_blocks = (int)((ntot / 16 + 255) / 256);
    conv_w_kernel<<<conv_blocks, 256>>>(W);

    dim3 grid((TOKENS_MAX + BM - 1) / BM, N_TILES);
    gemm_epilogue_kernel<<<grid, 256, SMEM_TOTAL>>>();

    final_kernel<<<1, 1024>>>((float*)d_out);
}